// round 8
// baseline (speedup 1.0000x reference)
#include <cuda_runtime.h>

#define CO 256
#define CI 256
#define SS 57      // effective max dilated kernel length
#define NW 12      // number of (k,d) combos
#define HEAD 28    // SS - (SS+1)/2

struct WPtrs { const float* w[NW]; };

// KD order = product(KS=[3,5,7,9], DS=[1,3,7])
__device__ __constant__ const int c_K[NW] = {3,3,3, 5,5,5, 7,7,7, 9,9,9};
__device__ __constant__ const int c_D[NW] = {1,3,7, 1,3,7, 1,3,7, 1,3,7};

// coef = softmax(alpha + gumbels); log_softmax drops (shift-invariant).
__device__ __forceinline__ void softmax12(const float* __restrict__ alpha,
                                          const float* __restrict__ gum,
                                          float* coef) {
    float l[NW];
    float m = -1e30f;
    #pragma unroll
    for (int i = 0; i < NW; i++) {
        l[i] = alpha[i] + gum[i];
        m = fmaxf(m, l[i]);
    }
    float s = 0.0f;
    #pragma unroll
    for (int i = 0; i < NW; i++) {
        l[i] = __expf(l[i] - m);
        s += l[i];
    }
    const float inv = 1.0f / s;
    #pragma unroll
    for (int i = 0; i < NW; i++) coef[i] = l[i] * inv;
}

// acc[s] = sum_i coef[i] * dilate(w_i, d_i) padded to SS, at position s
__device__ __forceinline__ float acc_at(const WPtrs& wp, const float* coef,
                                        unsigned row, int s) {
    float a = 0.0f;
    #pragma unroll
    for (int i = 0; i < NW; i++) {
        const int k = c_K[i];
        const int d = c_D[i];
        const int L = d * (k - 1) + 1;
        const int pl = (SS - L) >> 1;          // left pad
        const int t = s - pl;
        if (t >= 0 && t < L && (t % d) == 0)
            a += coef[i] * __ldg(&wp.w[i][row * k + t / d]);
    }
    return a;
}

// Scatter: warp per row. The interior [32, N-32) of every row is zeroed by
// cudaMemset2DAsync; this kernel writes ONLY the head line [0,32) and tail
// line [N-32,N) as full 128-byte float4 stores (coalesced, no partial-sector
// RMW). Disjoint from the memset region -> no ordering hazard.
__global__ void __launch_bounds__(256)
scatter_kernel(WPtrs wp,
               const float* __restrict__ alpha,
               const float* __restrict__ gum,
               float* __restrict__ out,
               int N) {
    __shared__ float sh[8][64];
    const int w = threadIdx.x >> 5;
    const int l = threadIdx.x & 31;
    const unsigned row = blockIdx.x * 8u + (unsigned)w;
    float* s = sh[w];

    float C[NW];
    softmax12(alpha, gum, C);

    s[l] = acc_at(wp, C, row, l);                                   // [0,32)
    s[l + 32] = (l + 32 < SS) ? acc_at(wp, C, row, l + 32) : 0.f;   // [32,64)
    __syncwarp();

    if (l < 16) {
        float* o = out + (size_t)row * (unsigned)N;
        float4 v;
        int j0;
        if (l < 8) {                       // head: j0 in [0,28]
            j0 = l << 2;
            v.x = (j0     <= HEAD) ? s[HEAD - j0]     : 0.f;
            v.y = (j0 + 1 <= HEAD) ? s[HEAD - j0 - 1] : 0.f;
            v.z = (j0 + 2 <= HEAD) ? s[HEAD - j0 - 2] : 0.f;
            v.w = (j0 + 3 <= HEAD) ? s[HEAD - j0 - 3] : 0.f;
        } else {                           // tail: j0 in [N-32, N-4]
            j0 = N - 64 + (l << 2);
            const int hi = N - HEAD;
            v.x = (j0     >= hi) ? s[N + HEAD - j0]     : 0.f;
            v.y = (j0 + 1 >= hi) ? s[N + HEAD - j0 - 1] : 0.f;
            v.z = (j0 + 2 >= hi) ? s[N + HEAD - j0 - 2] : 0.f;
            v.w = (j0 + 3 >= hi) ? s[N + HEAD - j0 - 3] : 0.f;
        }
        *reinterpret_cast<float4*>(o + j0) = v;
    }
}

// Fallback for N not multiple of 4 or N < 128: writes every element (no memset).
__global__ void __launch_bounds__(256)
multiconv_perm_fallback(WPtrs wp,
                        const float* __restrict__ alpha,
                        const float* __restrict__ gum,
                        float* __restrict__ out, int N) {
    __shared__ float sacc[SS];
    __shared__ float scoef[NW];
    const int tid = threadIdx.x;
    const unsigned row = blockIdx.x;
    if (tid == 0) softmax12(alpha, gum, scoef);
    __syncthreads();
    if (tid < SS) sacc[tid] = acc_at(wp, scoef, row, tid);
    __syncthreads();
    const size_t base = (size_t)row * (unsigned)N;
    const int hi = N - HEAD;
    for (int j = tid; j < N; j += 256) {
        out[base + j] = (j <= HEAD) ? sacc[HEAD - j]
                      : ((j >= hi) ? sacc[N + HEAD - j] : 0.0f);
    }
}

extern "C" void kernel_launch(void* const* d_in, const int* in_sizes, int n_in,
                              void* d_out, int out_size) {
    WPtrs wp;
    for (int i = 0; i < NW; i++) wp.w[i] = (const float*)d_in[i];
    const float* alpha = (const float*)d_in[12];
    const float* gum   = (const float*)d_in[13];
    const int N = out_size / (CO * CI);   // input_size, recovered host-side

    float* out = (float*)d_out;
    if ((N & 3) == 0 && N >= 128) {
        // 1) Driver fill path (~6.4 TB/s measured) zeroes row interiors only:
        //    for each of 65536 rows: bytes [128, 4*N-128) of that row.
        cudaMemset2DAsync(out + 32,                   // dst = first interior elt
                          (size_t)N * sizeof(float),  // pitch = row stride
                          0,
                          (size_t)(N - 64) * sizeof(float),  // width (bytes)
                          (size_t)(CO * CI));                // height (rows)
        // 2) Head/tail lines: full 128B stores, warp per row, disjoint region.
        scatter_kernel<<<(CO * CI) / 8, 256>>>(wp, alpha, gum, out, N);
    } else {
        multiconv_perm_fallback<<<CO * CI, 256>>>(wp, alpha, gum, out, N);
    }
}

// round 9
// speedup vs baseline: 1.4777x; 1.4777x over previous
#include <cuda_runtime.h>

#define CO 256
#define CI 256
#define SS 57      // effective max dilated kernel length
#define NW 12      // number of (k,d) combos
#define HEAD 28    // SS - (SS+1)/2

struct WPtrs { const float* w[NW]; };

__device__ __constant__ const int c_K[NW] = {3,3,3, 5,5,5, 7,7,7, 9,9,9};
__device__ __constant__ const int c_D[NW] = {1,3,7, 1,3,7, 1,3,7, 1,3,7};

// coef = softmax(alpha + gumbels); log_softmax drops (shift-invariant).
__device__ __forceinline__ void softmax12(const float* __restrict__ alpha,
                                          const float* __restrict__ gum,
                                          float* coef) {
    float l[NW];
    float m = -1e30f;
    #pragma unroll
    for (int i = 0; i < NW; i++) {
        l[i] = alpha[i] + gum[i];
        m = fmaxf(m, l[i]);
    }
    float s = 0.0f;
    #pragma unroll
    for (int i = 0; i < NW; i++) {
        l[i] = __expf(l[i] - m);
        s += l[i];
    }
    const float inv = 1.0f / s;
    #pragma unroll
    for (int i = 0; i < NW; i++) coef[i] = l[i] * inv;
}

// Scatter: 128 threads = 4 warps; each warp owns 32 rows (one per lane).
// Phase 1 (per lane, straight-line): compute the row's 23 nonzero values.
// Phase 2: stage into pos-major shared (stride 33: conflict-free both ways).
// Phase 3: warp stores 32 rows x two contiguous 128B lines (head [0,32),
// tail [N-32,N)) -- 1 wavefront per STG. Interior is zeroed by memset2D.
#define STRIDE 33
__global__ void __launch_bounds__(128)
scatter_kernel(WPtrs wp,
               const float* __restrict__ alpha,
               const float* __restrict__ gum,
               float* __restrict__ out,
               int N) {
    __shared__ float sh[4][64 * STRIDE];
    const int wid  = threadIdx.x >> 5;
    const int lane = threadIdx.x & 31;
    const unsigned rowBase = (blockIdx.x * 4u + (unsigned)wid) * 32u;
    const unsigned row = rowBase + (unsigned)lane;
    float* shw = sh[wid];

    float C[NW];
    softmax12(alpha, gum, C);

    // ---- straight-line tap loads (coalesced across lanes; L2-resident) ----
    float a[3], b[3], c[3], d[5], e[5], f[5], g[7], h[7], p[7];
    float q[9], r10[9], s9[9];
    {
        const float* w0  = wp.w[0]  + row * 3u;
        const float* w1  = wp.w[1]  + row * 3u;
        const float* w2  = wp.w[2]  + row * 3u;
        const float* w3  = wp.w[3]  + row * 5u;
        const float* w4  = wp.w[4]  + row * 5u;
        const float* w5  = wp.w[5]  + row * 5u;
        const float* w6  = wp.w[6]  + row * 7u;
        const float* w7  = wp.w[7]  + row * 7u;
        const float* w8  = wp.w[8]  + row * 7u;
        const float* w9  = wp.w[9]  + row * 9u;
        const float* w10 = wp.w[10] + row * 9u;
        const float* w11 = wp.w[11] + row * 9u;
        #pragma unroll
        for (int t = 0; t < 3; t++) { a[t]=__ldg(w0+t); b[t]=__ldg(w1+t); c[t]=__ldg(w2+t); }
        #pragma unroll
        for (int t = 0; t < 5; t++) { d[t]=__ldg(w3+t); e[t]=__ldg(w4+t); f[t]=__ldg(w5+t); }
        #pragma unroll
        for (int t = 0; t < 7; t++) { g[t]=__ldg(w6+t); h[t]=__ldg(w7+t); p[t]=__ldg(w8+t); }
        #pragma unroll
        for (int t = 0; t < 9; t++) { q[t]=__ldg(w9+t); r10[t]=__ldg(w10+t); s9[t]=__ldg(w11+t); }
    }

    // ---- 23 nonzero acc positions (tap->s map resolved at compile time) ----
    const float A0  = C[11]*s9[0];
    const float A7  = C[8]*p[0] + C[11]*s9[1];
    const float A14 = C[5]*f[0] + C[8]*p[1] + C[11]*s9[2];
    const float A16 = C[10]*r10[0];
    const float A19 = C[7]*h[0] + C[10]*r10[1];
    const float A21 = C[2]*c[0] + C[5]*f[1] + C[8]*p[2] + C[11]*s9[3];
    const float A22 = C[4]*e[0] + C[7]*h[1] + C[10]*r10[2];
    const float A24 = C[9]*q[0];
    const float A25 = C[1]*b[0] + C[4]*e[1] + C[6]*g[0] + C[7]*h[2] + C[9]*q[1] + C[10]*r10[3];
    const float A26 = C[3]*d[0] + C[6]*g[1] + C[9]*q[2];
    const float A27 = C[0]*a[0] + C[3]*d[1] + C[6]*g[2] + C[9]*q[3];
    const float A28 = C[0]*a[1] + C[1]*b[1] + C[2]*c[1] + C[3]*d[2] + C[4]*e[2] + C[5]*f[2]
                    + C[6]*g[3] + C[7]*h[3] + C[8]*p[3] + C[9]*q[4] + C[10]*r10[4] + C[11]*s9[4];
    const float A29 = C[0]*a[2] + C[3]*d[3] + C[6]*g[4] + C[9]*q[5];
    const float A30 = C[3]*d[4] + C[6]*g[5] + C[9]*q[6];
    const float A31 = C[1]*b[2] + C[4]*e[3] + C[6]*g[6] + C[7]*h[4] + C[9]*q[7] + C[10]*r10[5];
    const float A32 = C[9]*q[8];
    const float A34 = C[4]*e[4] + C[7]*h[5] + C[10]*r10[6];
    const float A35 = C[2]*c[2] + C[5]*f[3] + C[8]*p[4] + C[11]*s9[5];
    const float A37 = C[7]*h[6] + C[10]*r10[7];
    const float A40 = C[10]*r10[8];
    const float A42 = C[5]*f[4] + C[8]*p[5] + C[11]*s9[6];
    const float A49 = C[8]*p[6] + C[11]*s9[7];
    const float A56 = C[11]*s9[8];

    // ---- stage: pos-major, sh[pos*33 + lane]. slot 0..31 = head (out[j]),
    //      slot 32..63 = tail (out[N-32+v], slot = 32+v) ----
    #define PUT(pos, val) shw[(pos) * STRIDE + lane] = (val)
    PUT(0,A28);  PUT(1,A27);  PUT(2,A26);  PUT(3,A25);  PUT(4,A24);  PUT(5,0.f);
    PUT(6,A22);  PUT(7,A21);  PUT(8,0.f);  PUT(9,A19);  PUT(10,0.f); PUT(11,0.f);
    PUT(12,A16); PUT(13,0.f); PUT(14,A14); PUT(15,0.f); PUT(16,0.f); PUT(17,0.f);
    PUT(18,0.f); PUT(19,0.f); PUT(20,0.f); PUT(21,A7);  PUT(22,0.f); PUT(23,0.f);
    PUT(24,0.f); PUT(25,0.f); PUT(26,0.f); PUT(27,0.f); PUT(28,A0);  PUT(29,0.f);
    PUT(30,0.f); PUT(31,0.f);
    PUT(32,0.f); PUT(33,0.f); PUT(34,0.f); PUT(35,0.f); PUT(36,A56); PUT(37,0.f);
    PUT(38,0.f); PUT(39,0.f); PUT(40,0.f); PUT(41,0.f); PUT(42,0.f); PUT(43,A49);
    PUT(44,0.f); PUT(45,0.f); PUT(46,0.f); PUT(47,0.f); PUT(48,0.f); PUT(49,0.f);
    PUT(50,A42); PUT(51,0.f); PUT(52,A40); PUT(53,0.f); PUT(54,0.f); PUT(55,A37);
    PUT(56,0.f); PUT(57,A35); PUT(58,A34); PUT(59,0.f); PUT(60,A32); PUT(61,A31);
    PUT(62,A30); PUT(63,A29);
    #undef PUT
    __syncwarp();

    // ---- store: 32 rows x (head line + tail line), each 128B contiguous ----
    #pragma unroll 8
    for (int r = 0; r < 32; r++) {
        float* o = out + (size_t)(rowBase + r) * (unsigned)N;
        o[lane]          = shw[lane * STRIDE + r];           // head [0,32)
        o[N - 32 + lane] = shw[(lane + 32) * STRIDE + r];    // tail [N-32,N)
    }
}

// Fallback for N < 64: write everything (no memset).
__global__ void __launch_bounds__(256)
multiconv_perm_fallback(WPtrs wp,
                        const float* __restrict__ alpha,
                        const float* __restrict__ gum,
                        float* __restrict__ out, int N) {
    __shared__ float sacc[SS];
    __shared__ float scoef[NW];
    const int tid = threadIdx.x;
    const unsigned row = blockIdx.x;
    if (tid == 0) softmax12(alpha, gum, scoef);
    __syncthreads();
    if (tid < SS) {
        float acc = 0.0f;
        #pragma unroll
        for (int i = 0; i < NW; i++) {
            const int k = c_K[i];
            const int d = c_D[i];
            const int L = d * (k - 1) + 1;
            const int pl = (SS - L) >> 1;
            const int tt = tid - pl;
            if (tt >= 0 && tt < L && (tt % d) == 0)
                acc += scoef[i] * __ldg(&wp.w[i][row * k + tt / d]);
        }
        sacc[tid] = acc;
    }
    __syncthreads();
    const size_t base = (size_t)row * (unsigned)N;
    const int hi = N - HEAD;
    for (int j = tid; j < N; j += 256) {
        out[base + j] = (j <= HEAD) ? sacc[HEAD - j]
                      : ((j >= hi) ? sacc[N + HEAD - j] : 0.0f);
    }
}

extern "C" void kernel_launch(void* const* d_in, const int* in_sizes, int n_in,
                              void* d_out, int out_size) {
    WPtrs wp;
    for (int i = 0; i < NW; i++) wp.w[i] = (const float*)d_in[i];
    const float* alpha = (const float*)d_in[12];
    const float* gum   = (const float*)d_in[13];
    const int N = out_size / (CO * CI);   // input_size, recovered host-side

    float* out = (float*)d_out;
    if (N >= 64) {
        // 1) Driver fill path (~6.4 TB/s measured) zeroes row interiors:
        //    for each row, bytes [128, 4N-128).
        if (N > 64) {
            cudaMemset2DAsync(out + 32,
                              (size_t)N * sizeof(float),         // pitch
                              0,
                              (size_t)(N - 64) * sizeof(float),  // width
                              (size_t)(CO * CI));                // height
        }
        // 2) Head/tail lines only, fully coalesced. Disjoint region.
        scatter_kernel<<<(CO * CI) / 128, 128>>>(wp, alpha, gum, out, N);
    } else {
        multiconv_perm_fallback<<<CO * CI, 256>>>(wp, alpha, gum, out, N);
    }
}

// round 10
// speedup vs baseline: 1.6590x; 1.1227x over previous
#include <cuda_runtime.h>

#define CO 256
#define CI 256
#define SS 57      // effective max dilated kernel length
#define NW 12      // number of (k,d) combos
#define HEAD 28    // SS - (SS+1)/2

struct WPtrs { const float* w[NW]; };

__device__ __constant__ const int c_K[NW] = {3,3,3, 5,5,5, 7,7,7, 9,9,9};
__device__ __constant__ const int c_D[NW] = {1,3,7, 1,3,7, 1,3,7, 1,3,7};

// coef = softmax(alpha + gumbels); log_softmax drops (shift-invariant).
__device__ __forceinline__ void softmax12(const float* __restrict__ alpha,
                                          const float* __restrict__ gum,
                                          float* coef) {
    float l[NW];
    float m = -1e30f;
    #pragma unroll
    for (int i = 0; i < NW; i++) {
        l[i] = alpha[i] + gum[i];
        m = fmaxf(m, l[i]);
    }
    float s = 0.0f;
    #pragma unroll
    for (int i = 0; i < NW; i++) {
        l[i] = __expf(l[i] - m);
        s += l[i];
    }
    const float inv = 1.0f / s;
    #pragma unroll
    for (int i = 0; i < NW; i++) coef[i] = l[i] * inv;
}

// Scatter: 128 threads = 4 warps; each warp owns 32 rows (one per lane).
// Phase 1 (per lane, straight-line): compute the row's 23 nonzero values.
// Phase 2: stage into pos-major shared (stride 33: conflict-free both ways).
// Phase 3: warp stores 32 rows x two contiguous 128B lines (head [0,32),
// tail [N-32,N)). Interior is zeroed by memset2D (disjoint region).
#define STRIDE 33
__global__ void __launch_bounds__(128)
scatter_kernel(WPtrs wp,
               const float* __restrict__ alpha,
               const float* __restrict__ gum,
               float* __restrict__ out,
               int N) {
    __shared__ float sh[4][64 * STRIDE];
    const int wid  = threadIdx.x >> 5;
    const int lane = threadIdx.x & 31;
    const unsigned rowBase = (blockIdx.x * 4u + (unsigned)wid) * 32u;
    const unsigned row = rowBase + (unsigned)lane;
    float* shw = sh[wid];

    float C[NW];
    softmax12(alpha, gum, C);

    // ---- straight-line tap loads (coalesced across lanes; L2-resident) ----
    float a[3], b[3], c[3], d[5], e[5], f[5], g[7], h[7], p[7];
    float q[9], r10[9], s9[9];
    {
        const float* w0  = wp.w[0]  + row * 3u;
        const float* w1  = wp.w[1]  + row * 3u;
        const float* w2  = wp.w[2]  + row * 3u;
        const float* w3  = wp.w[3]  + row * 5u;
        const float* w4  = wp.w[4]  + row * 5u;
        const float* w5  = wp.w[5]  + row * 5u;
        const float* w6  = wp.w[6]  + row * 7u;
        const float* w7  = wp.w[7]  + row * 7u;
        const float* w8  = wp.w[8]  + row * 7u;
        const float* w9  = wp.w[9]  + row * 9u;
        const float* w10 = wp.w[10] + row * 9u;
        const float* w11 = wp.w[11] + row * 9u;
        #pragma unroll
        for (int t = 0; t < 3; t++) { a[t]=__ldg(w0+t); b[t]=__ldg(w1+t); c[t]=__ldg(w2+t); }
        #pragma unroll
        for (int t = 0; t < 5; t++) { d[t]=__ldg(w3+t); e[t]=__ldg(w4+t); f[t]=__ldg(w5+t); }
        #pragma unroll
        for (int t = 0; t < 7; t++) { g[t]=__ldg(w6+t); h[t]=__ldg(w7+t); p[t]=__ldg(w8+t); }
        #pragma unroll
        for (int t = 0; t < 9; t++) { q[t]=__ldg(w9+t); r10[t]=__ldg(w10+t); s9[t]=__ldg(w11+t); }
    }

    // ---- 23 nonzero acc positions (tap->s map resolved at compile time) ----
    const float A0  = C[11]*s9[0];
    const float A7  = C[8]*p[0] + C[11]*s9[1];
    const float A14 = C[5]*f[0] + C[8]*p[1] + C[11]*s9[2];
    const float A16 = C[10]*r10[0];
    const float A19 = C[7]*h[0] + C[10]*r10[1];
    const float A21 = C[2]*c[0] + C[5]*f[1] + C[8]*p[2] + C[11]*s9[3];
    const float A22 = C[4]*e[0] + C[7]*h[1] + C[10]*r10[2];
    const float A24 = C[9]*q[0];
    const float A25 = C[1]*b[0] + C[4]*e[1] + C[6]*g[0] + C[7]*h[2] + C[9]*q[1] + C[10]*r10[3];
    const float A26 = C[3]*d[0] + C[6]*g[1] + C[9]*q[2];
    const float A27 = C[0]*a[0] + C[3]*d[1] + C[6]*g[2] + C[9]*q[3];
    const float A28 = C[0]*a[1] + C[1]*b[1] + C[2]*c[1] + C[3]*d[2] + C[4]*e[2] + C[5]*f[2]
                    + C[6]*g[3] + C[7]*h[3] + C[8]*p[3] + C[9]*q[4] + C[10]*r10[4] + C[11]*s9[4];
    const float A29 = C[0]*a[2] + C[3]*d[3] + C[6]*g[4] + C[9]*q[5];
    const float A30 = C[3]*d[4] + C[6]*g[5] + C[9]*q[6];
    const float A31 = C[1]*b[2] + C[4]*e[3] + C[6]*g[6] + C[7]*h[4] + C[9]*q[7] + C[10]*r10[5];
    const float A32 = C[9]*q[8];
    const float A34 = C[4]*e[4] + C[7]*h[5] + C[10]*r10[6];
    const float A35 = C[2]*c[2] + C[5]*f[3] + C[8]*p[4] + C[11]*s9[5];
    const float A37 = C[7]*h[6] + C[10]*r10[7];
    const float A40 = C[10]*r10[8];
    const float A42 = C[5]*f[4] + C[8]*p[5] + C[11]*s9[6];
    const float A49 = C[8]*p[6] + C[11]*s9[7];
    const float A56 = C[11]*s9[8];

    // ---- stage: pos-major, sh[pos*33 + lane]. slot 0..31 = head (out[j]),
    //      slot 32..63 = tail (out[N-32+v], slot = 32+v) ----
    #define PUT(pos, val) shw[(pos) * STRIDE + lane] = (val)
    PUT(0,A28);  PUT(1,A27);  PUT(2,A26);  PUT(3,A25);  PUT(4,A24);  PUT(5,0.f);
    PUT(6,A22);  PUT(7,A21);  PUT(8,0.f);  PUT(9,A19);  PUT(10,0.f); PUT(11,0.f);
    PUT(12,A16); PUT(13,0.f); PUT(14,A14); PUT(15,0.f); PUT(16,0.f); PUT(17,0.f);
    PUT(18,0.f); PUT(19,0.f); PUT(20,0.f); PUT(21,A7);  PUT(22,0.f); PUT(23,0.f);
    PUT(24,0.f); PUT(25,0.f); PUT(26,0.f); PUT(27,0.f); PUT(28,A0);  PUT(29,0.f);
    PUT(30,0.f); PUT(31,0.f);
    PUT(32,0.f); PUT(33,0.f); PUT(34,0.f); PUT(35,0.f); PUT(36,A56); PUT(37,0.f);
    PUT(38,0.f); PUT(39,0.f); PUT(40,0.f); PUT(41,0.f); PUT(42,0.f); PUT(43,A49);
    PUT(44,0.f); PUT(45,0.f); PUT(46,0.f); PUT(47,0.f); PUT(48,0.f); PUT(49,0.f);
    PUT(50,A42); PUT(51,0.f); PUT(52,A40); PUT(53,0.f); PUT(54,0.f); PUT(55,A37);
    PUT(56,0.f); PUT(57,A35); PUT(58,A34); PUT(59,0.f); PUT(60,A32); PUT(61,A31);
    PUT(62,A30); PUT(63,A29);
    #undef PUT
    __syncwarp();

    // ---- store: 32 rows x (head line + tail line), each 128B contiguous ----
    #pragma unroll 8
    for (int r = 0; r < 32; r++) {
        float* o = out + (size_t)(rowBase + r) * (unsigned)N;
        o[lane]          = shw[lane * STRIDE + r];           // head [0,32)
        o[N - 32 + lane] = shw[(lane + 32) * STRIDE + r];    // tail [N-32,N)
    }
}

// Fallback for N < 64: write everything (no memset).
__global__ void __launch_bounds__(256)
multiconv_perm_fallback(WPtrs wp,
                        const float* __restrict__ alpha,
                        const float* __restrict__ gum,
                        float* __restrict__ out, int N) {
    __shared__ float sacc[SS];
    __shared__ float scoef[NW];
    const int tid = threadIdx.x;
    const unsigned row = blockIdx.x;
    if (tid == 0) softmax12(alpha, gum, scoef);
    __syncthreads();
    if (tid < SS) {
        float acc = 0.0f;
        #pragma unroll
        for (int i = 0; i < NW; i++) {
            const int k = c_K[i];
            const int d = c_D[i];
            const int L = d * (k - 1) + 1;
            const int pl = (SS - L) >> 1;
            const int tt = tid - pl;
            if (tt >= 0 && tt < L && (tt % d) == 0)
                acc += scoef[i] * __ldg(&wp.w[i][row * k + tt / d]);
        }
        sacc[tid] = acc;
    }
    __syncthreads();
    const size_t base = (size_t)row * (unsigned)N;
    const int hi = N - HEAD;
    for (int j = tid; j < N; j += 256) {
        out[base + j] = (j <= HEAD) ? sacc[HEAD - j]
                      : ((j >= hi) ? sacc[N + HEAD - j] : 0.0f);
    }
}

extern "C" void kernel_launch(void* const* d_in, const int* in_sizes, int n_in,
                              void* d_out, int out_size) {
    WPtrs wp;
    for (int i = 0; i < NW; i++) wp.w[i] = (const float*)d_in[i];
    const float* alpha = (const float*)d_in[12];
    const float* gum   = (const float*)d_in[13];
    const int N = out_size / (CO * CI);   // input_size, recovered host-side

    float* out = (float*)d_out;
    if (N > 64) {
        // Fork/join: the memset (interior [32,N-32) per row) and the scatter
        // (head/tail lines) write DISJOINT regions, so they run as parallel
        // graph branches. Stream/event creation is host-side only (no device
        // allocations); handles are intentionally not destroyed during
        // capture. kernel_launch is invoked O(1) times, so the leak is bounded.
        cudaStream_t s2;
        cudaStreamCreate(&s2);
        cudaEvent_t evFork, evJoin;
        cudaEventCreateWithFlags(&evFork, cudaEventDisableTiming);
        cudaEventCreateWithFlags(&evJoin, cudaEventDisableTiming);

        cudaEventRecord(evFork, 0);            // fork from capture stream
        cudaStreamWaitEvent(s2, evFork, 0);

        // Branch A (side stream): head/tail scatter, fully coalesced lines.
        scatter_kernel<<<(CO * CI) / 128, 128, 0, s2>>>(wp, alpha, gum, out, N);
        cudaEventRecord(evJoin, s2);

        // Branch B (main stream): driver fill path (~6.4 TB/s measured)
        // zeroes row interiors: for each row, bytes [128, 4N-128).
        cudaMemset2DAsync(out + 32,
                          (size_t)N * sizeof(float),         // pitch
                          0,
                          (size_t)(N - 64) * sizeof(float),  // width
                          (size_t)(CO * CI),                 // height
                          0);

        cudaStreamWaitEvent(0, evJoin, 0);     // join
    } else if (N == 64) {
        // No interior: scatter covers the whole row.
        scatter_kernel<<<(CO * CI) / 128, 128>>>(wp, alpha, gum, out, N);
    } else {
        multiconv_perm_fallback<<<CO * CI, 256>>>(wp, alpha, gum, out, N);
    }
}